// round 2
// baseline (speedup 1.0000x reference)
#include <cuda_runtime.h>
#include <cuda_bf16.h>
#include <mma.h>
#include <math.h>
#include <float.h>

using namespace nvcuda;

// ---------------- problem constants ----------------
#define H    512
#define H2   1024      // 2H
#define H4   2048      // 4H
#define E    256
#define V3   50003
#define TK   4096

// output layout (flattened tuple, in order)
#define OFF_FINAL 0
#define OFF_H     (V3)                  // 50003
#define OFF_C     (OFF_H + H)           // 50515
#define OFF_CT    (OFF_C + H)           // 51027
#define OFF_ATTN  (OFF_CT + H2)         // 52051
#define OFF_PGEN  (OFF_ATTN + TK)       // 56147
#define OFF_COV   (OFF_PGEN + 1)        // 56148

// ---------------- device scratch ----------------
__device__ float g_x[E];
__device__ float g_gates[H4];
__device__ float g_h[H];
__device__ float g_c[H];
__device__ float g_dec_feat[H2];
__device__ float g_scores[TK];
__device__ float g_attn[TK];
__device__ float g_ct[H2];
__device__ float g_out1[H];
__device__ float g_logits[V3];
__device__ float g_pgen;
__device__ float g_vmax;
__device__ float g_vsum;

__device__ __forceinline__ float warp_sum(float s) {
    #pragma unroll
    for (int o = 16; o > 0; o >>= 1) s += __shfl_down_sync(0xffffffffu, s, o);
    return s;
}

__device__ __forceinline__ float sigm(float x) { return 1.0f / (1.0f + expf(-x)); }

// ---------------- K1: x = W_xc @ [c_t_1, embd] + b_xc ----------------
__global__ __launch_bounds__(256) void k_x(
        const float* __restrict__ c_t_1, const float* __restrict__ emb,
        const float* __restrict__ W_xc, const float* __restrict__ b_xc,
        const int* __restrict__ dec_in) {
    int o = blockIdx.x * 8 + (threadIdx.x >> 5);
    int lane = threadIdx.x & 31;
    if (o >= E) return;
    const float* erow = emb + (size_t)dec_in[0] * E;
    const float* wrow = W_xc + (size_t)o * (H2 + E);
    float s = 0.f;
    for (int j = lane; j < H2 + E; j += 32) {
        float v = (j < H2) ? c_t_1[j] : erow[j - H2];
        s += wrow[j] * v;
    }
    s = warp_sum(s);
    if (lane == 0) g_x[o] = s + b_xc[o];
}

// ---------------- K2: gates = W_ih@x + W_hh@h0 + b_ih + b_hh ----------------
__global__ __launch_bounds__(256) void k_gates(
        const float* __restrict__ h0,
        const float* __restrict__ W_ih, const float* __restrict__ W_hh,
        const float* __restrict__ b_ih, const float* __restrict__ b_hh) {
    int o = blockIdx.x * 8 + (threadIdx.x >> 5);
    int lane = threadIdx.x & 31;
    if (o >= H4) return;
    const float* wi = W_ih + (size_t)o * E;
    const float* wh = W_hh + (size_t)o * H;
    float s = 0.f;
    #pragma unroll
    for (int j = lane; j < E; j += 32) s += wi[j] * g_x[j];
    for (int j = lane; j < H; j += 32) s += wh[j] * h0[j];
    s = warp_sum(s);
    if (lane == 0) g_gates[o] = s + b_ih[o] + b_hh[o];
}

// ---------------- K3: LSTM combine + zero accumulators ----------------
__global__ __launch_bounds__(512) void k_lstm(const float* __restrict__ c0,
                                              float* __restrict__ out) {
    int m = threadIdx.x;           // 512 threads
    float ig = g_gates[m];
    float fg = g_gates[H + m];
    float gg = g_gates[2 * H + m];
    float og = g_gates[3 * H + m];
    float cn = sigm(fg) * c0[m] + sigm(ig) * tanhf(gg);
    float hn = sigm(og) * tanhf(cn);
    g_c[m] = cn; g_h[m] = hn;
    out[OFF_H + m] = hn;
    out[OFF_C + m] = cn;
    // zero score + context accumulators for the atomic-accumulate kernels
    #pragma unroll
    for (int t = m; t < TK; t += H) g_scores[t] = 0.f;
    g_ct[m] = 0.f; g_ct[m + H] = 0.f;
}

// ---------------- K4: dec_feat = W_dp @ [h_new, c_new] + b_dp ----------------
__global__ __launch_bounds__(256) void k_dec_feat(const float* __restrict__ W_dp,
                                                  const float* __restrict__ b_dp) {
    int o = blockIdx.x * 8 + (threadIdx.x >> 5);
    int lane = threadIdx.x & 31;
    if (o >= H2) return;
    const float* wr = W_dp + (size_t)o * H2;
    float s = 0.f;
    for (int j = lane; j < H2; j += 32) {
        float v = (j < H) ? g_h[j] : g_c[j - H];
        s += wr[j] * v;
    }
    s = warp_sum(s);
    if (lane == 0) g_dec_feat[o] = s + b_dp[o];
}

// ---------------- K5: fused attention GEMM (tf32 WMMA) ----------------
// scores[t] += sum_m v[m] * tanh( (enc @ W_h^T)[t,m] + dec_feat[m] + cov[t]*w_c[m] )
// tile: 64 t  x  64 m, K=1024 chunked by 32
__global__ __launch_bounds__(256) void k_attn_gemm(
        const float* __restrict__ enc, const float* __restrict__ W_h,
        const float* __restrict__ coverage,
        const float* __restrict__ w_c, const float* __restrict__ v_att) {
    __shared__ float As[64][36];
    __shared__ float Bs[64][36];
    __shared__ float Cs[64][68];
    __shared__ float sDec[64], sWc[64], sV[64], sCov[64];

    const int tid = threadIdx.x;
    const int m0 = blockIdx.x * 64;
    const int t0 = blockIdx.y * 64;
    const int w  = tid >> 5;
    const int wt = w & 3;       // t sub-tile (16 rows)
    const int wm = w >> 2;      // m sub-tile (32 cols)

    if (tid < 64) {
        sDec[tid] = g_dec_feat[m0 + tid];
        sWc[tid]  = w_c[m0 + tid];
        sV[tid]   = v_att[m0 + tid];
        sCov[tid] = coverage[t0 + tid];
    }

    wmma::fragment<wmma::accumulator, 16, 16, 8, float> acc[2];
    wmma::fill_fragment(acc[0], 0.0f);
    wmma::fill_fragment(acc[1], 0.0f);

    const int row = tid >> 2;      // 0..63
    const int c4  = tid & 3;       // 0..3

    for (int k0 = 0; k0 < H2; k0 += 32) {
        __syncthreads();
        const float4* pa = reinterpret_cast<const float4*>(enc + (size_t)(t0 + row) * H2 + k0);
        const float4* pb = reinterpret_cast<const float4*>(W_h + (size_t)(m0 + row) * H2 + k0);
        *reinterpret_cast<float4*>(&As[row][c4 * 4])        = pa[c4];
        *reinterpret_cast<float4*>(&As[row][16 + c4 * 4])   = pa[c4 + 4];
        *reinterpret_cast<float4*>(&Bs[row][c4 * 4])        = pb[c4];
        *reinterpret_cast<float4*>(&Bs[row][16 + c4 * 4])   = pb[c4 + 4];
        __syncthreads();

        #pragma unroll
        for (int kk = 0; kk < 32; kk += 8) {
            wmma::fragment<wmma::matrix_a, 16, 16, 8, wmma::precision::tf32, wmma::row_major> a;
            wmma::load_matrix_sync(a, &As[wt * 16][kk], 36);
            #pragma unroll
            for (int i = 0; i < a.num_elements; i++) a.x[i] = wmma::__float_to_tf32(a.x[i]);
            #pragma unroll
            for (int j = 0; j < 2; j++) {
                wmma::fragment<wmma::matrix_b, 16, 16, 8, wmma::precision::tf32, wmma::col_major> b;
                wmma::load_matrix_sync(b, &Bs[wm * 32 + j * 16][kk], 36);
                #pragma unroll
                for (int i = 0; i < b.num_elements; i++) b.x[i] = wmma::__float_to_tf32(b.x[i]);
                wmma::mma_sync(acc[j], a, b, acc[j]);
            }
        }
    }

    __syncthreads();
    wmma::store_matrix_sync(&Cs[wt * 16][wm * 32],      acc[0], 68, wmma::mem_row_major);
    wmma::store_matrix_sync(&Cs[wt * 16][wm * 32 + 16], acc[1], 68, wmma::mem_row_major);
    __syncthreads();

    // epilogue: tanh + v-weighted reduce over 64 m-cols, 4 threads per row
    const int tr = tid >> 2;
    const int q  = tid & 3;
    const float covt = sCov[tr];
    float s = 0.f;
    #pragma unroll
    for (int mm = q * 16; mm < q * 16 + 16; mm++) {
        float val = Cs[tr][mm] + sDec[mm] + covt * sWc[mm];
        s += sV[mm] * tanhf(val);
    }
    s += __shfl_down_sync(0xffffffffu, s, 2, 4);
    s += __shfl_down_sync(0xffffffffu, s, 1, 4);
    if (q == 0) atomicAdd(&g_scores[t0 + tr], s);
}

// ---------------- K6: softmax over scores -> attn, coverage_next ----------------
__global__ __launch_bounds__(1024) void k_softmax(const float* __restrict__ coverage,
                                                  float* __restrict__ out) {
    __shared__ float red[32];
    __shared__ float ebuf[TK];
    const int tid = threadIdx.x;   // 1024 threads
    float v[4];
    float lm = -FLT_MAX;
    #pragma unroll
    for (int i = 0; i < 4; i++) { v[i] = g_scores[tid + i * 1024]; lm = fmaxf(lm, v[i]); }
    #pragma unroll
    for (int o = 16; o > 0; o >>= 1) lm = fmaxf(lm, __shfl_down_sync(0xffffffffu, lm, o));
    if ((tid & 31) == 0) red[tid >> 5] = lm;
    __syncthreads();
    if (tid < 32) {
        float x = red[tid];
        #pragma unroll
        for (int o = 16; o > 0; o >>= 1) x = fmaxf(x, __shfl_down_sync(0xffffffffu, x, o));
        if (tid == 0) red[0] = x;
    }
    __syncthreads();
    const float mx = red[0];
    __syncthreads();
    float ls = 0.f;
    #pragma unroll
    for (int i = 0; i < 4; i++) { float e = expf(v[i] - mx); ebuf[tid + i * 1024] = e; ls += e; }
    ls = warp_sum(ls);
    if ((tid & 31) == 0) red[tid >> 5] = ls;
    __syncthreads();
    if (tid < 32) {
        float x = red[tid];
        x = warp_sum(x);
        if (tid == 0) red[0] = x;
    }
    __syncthreads();
    const float inv = 1.0f / red[0];
    #pragma unroll
    for (int i = 0; i < 4; i++) {
        int idx = tid + i * 1024;
        float a = ebuf[idx] * inv;
        g_attn[idx] = a;
        out[OFF_ATTN + idx] = a;
        out[OFF_COV + idx]  = coverage[idx] + a;
    }
}

// ---------------- K7: c_t = attn @ enc (partial accumulate) ----------------
__global__ __launch_bounds__(256) void k_context(const float* __restrict__ enc) {
    const int t0 = blockIdx.x * 32;      // 128 blocks x 32 timesteps
    const int nb = threadIdx.x * 4;      // 256 threads cover 1024 cols
    float4 acc = make_float4(0.f, 0.f, 0.f, 0.f);
    #pragma unroll
    for (int tt = 0; tt < 32; tt++) {
        float a = g_attn[t0 + tt];
        float4 e = *reinterpret_cast<const float4*>(enc + (size_t)(t0 + tt) * H2 + nb);
        acc.x += a * e.x; acc.y += a * e.y; acc.z += a * e.z; acc.w += a * e.w;
    }
    atomicAdd(&g_ct[nb + 0], acc.x);
    atomicAdd(&g_ct[nb + 1], acc.y);
    atomicAdd(&g_ct[nb + 2], acc.z);
    atomicAdd(&g_ct[nb + 3], acc.w);
}

// ---------------- K8: out1 rows (blocks 0..63) + p_gen & c_t writeout (block 64) ----------------
__global__ __launch_bounds__(256) void k_out1_pgen(
        const float* __restrict__ W_o1, const float* __restrict__ b_o1,
        const float* __restrict__ W_pg, const float* __restrict__ b_pg,
        float* __restrict__ out) {
    const int tid = threadIdx.x;
    if (blockIdx.x < 64) {
        int o = blockIdx.x * 8 + (tid >> 5);
        int lane = tid & 31;
        const float* wr = W_o1 + (size_t)o * (3 * H);
        float s = 0.f;
        for (int j = lane; j < 3 * H; j += 32) {
            float v = (j < H) ? g_h[j] : g_ct[j - H];
            s += wr[j] * v;
        }
        s = warp_sum(s);
        if (lane == 0) g_out1[o] = s + b_o1[o];
    } else {
        __shared__ float red[8];
        float s = 0.f;
        for (int j = tid; j < H4 + E; j += 256) {
            float v;
            if (j < H2)            v = g_ct[j];
            else if (j < H2 + H)   v = g_h[j - H2];
            else if (j < H4)       v = g_c[j - H2 - H];
            else                   v = g_x[j - H4];
            s += W_pg[j] * v;
        }
        s = warp_sum(s);
        if ((tid & 31) == 0) red[tid >> 5] = s;
        __syncthreads();
        if (tid == 0) {
            float x = 0.f;
            #pragma unroll
            for (int i = 0; i < 8; i++) x += red[i];
            float p = sigm(x + b_pg[0]);
            g_pgen = p; out[OFF_PGEN] = p;
        }
        #pragma unroll
        for (int i = 0; i < 4; i++) out[OFF_CT + tid * 4 + i] = g_ct[tid * 4 + i];
    }
}

// ---------------- K9: logits = W_o2 @ out1 + b_o2 ----------------
__global__ __launch_bounds__(256) void k_logits(const float* __restrict__ W_o2,
                                                const float* __restrict__ b_o2) {
    __shared__ float sx[H];
    const int tid = threadIdx.x;
    sx[tid] = g_out1[tid]; sx[tid + 256] = g_out1[tid + 256];
    __syncthreads();
    const int v = blockIdx.x * 8 + (tid >> 5);
    const int lane = tid & 31;
    if (v < V3) {
        const float4* wr = reinterpret_cast<const float4*>(W_o2 + (size_t)v * H);
        const float4* xr = reinterpret_cast<const float4*>(sx);
        float s = 0.f;
        #pragma unroll
        for (int i = 0; i < 4; i++) {
            float4 w4 = wr[lane + 32 * i];
            float4 x4 = xr[lane + 32 * i];
            s += w4.x * x4.x + w4.y * x4.y + w4.z * x4.z + w4.w * x4.w;
        }
        s = warp_sum(s);
        if (lane == 0) g_logits[v] = s + b_o2[v];
    }
}

// ---------------- K10: vocab softmax reduction (max, sumexp) ----------------
__global__ __launch_bounds__(1024) void k_vred() {
    __shared__ float red[32];
    const int tid = threadIdx.x;  // 1024
    float lm = -FLT_MAX;
    for (int v = tid; v < V3; v += 1024) lm = fmaxf(lm, g_logits[v]);
    #pragma unroll
    for (int o = 16; o > 0; o >>= 1) lm = fmaxf(lm, __shfl_down_sync(0xffffffffu, lm, o));
    if ((tid & 31) == 0) red[tid >> 5] = lm;
    __syncthreads();
    if (tid < 32) {
        float x = red[tid];
        #pragma unroll
        for (int o = 16; o > 0; o >>= 1) x = fmaxf(x, __shfl_down_sync(0xffffffffu, x, o));
        if (tid == 0) red[0] = x;
    }
    __syncthreads();
    const float mx = red[0];
    __syncthreads();
    float ls = 0.f;
    for (int v = tid; v < V3; v += 1024) ls += expf(g_logits[v] - mx);
    ls = warp_sum(ls);
    if ((tid & 31) == 0) red[tid >> 5] = ls;
    __syncthreads();
    if (tid < 32) {
        float x = red[tid];
        x = warp_sum(x);
        if (tid == 0) { g_vmax = mx; g_vsum = x; }
    }
}

// ---------------- K11: final_dist base = p_gen * vocab_softmax ----------------
__global__ __launch_bounds__(256) void k_final(float* __restrict__ out) {
    int v = blockIdx.x * blockDim.x + threadIdx.x;
    if (v < V3) out[v] = g_pgen * expf(g_logits[v] - g_vmax) / g_vsum;
}

// ---------------- K12: scatter add (1-p_gen)*attn at input_idx ----------------
__global__ __launch_bounds__(256) void k_scatter(const int* __restrict__ input_idx,
                                                 float* __restrict__ out) {
    int t = blockIdx.x * blockDim.x + threadIdx.x;
    if (t < TK) atomicAdd(&out[input_idx[t]], (1.0f - g_pgen) * g_attn[t]);
}

// ---------------- launch ----------------
extern "C" void kernel_launch(void* const* d_in, const int* in_sizes, int n_in,
                              void* d_out, int out_size) {
    const float* enc      = (const float*)d_in[0];
    const float* c_t_1    = (const float*)d_in[1];
    const float* h0       = (const float*)d_in[2];
    const float* c0       = (const float*)d_in[3];
    const float* coverage = (const float*)d_in[4];
    const float* emb      = (const float*)d_in[5];
    const float* W_xc     = (const float*)d_in[6];
    const float* b_xc     = (const float*)d_in[7];
    const float* W_ih     = (const float*)d_in[8];
    const float* W_hh     = (const float*)d_in[9];
    const float* b_ih     = (const float*)d_in[10];
    const float* b_hh     = (const float*)d_in[11];
    const float* W_h      = (const float*)d_in[12];
    const float* W_dp     = (const float*)d_in[13];
    const float* b_dp     = (const float*)d_in[14];
    const float* w_c      = (const float*)d_in[15];
    const float* v_att    = (const float*)d_in[16];
    const float* W_pg     = (const float*)d_in[17];
    const float* b_pg     = (const float*)d_in[18];
    const float* W_o1     = (const float*)d_in[19];
    const float* b_o1     = (const float*)d_in[20];
    const float* W_o2     = (const float*)d_in[21];
    const float* b_o2     = (const float*)d_in[22];
    const int*   dec_in   = (const int*)d_in[23];
    const int*   in_idx   = (const int*)d_in[24];
    float* out = (float*)d_out;

    k_x<<<32, 256>>>(c_t_1, emb, W_xc, b_xc, dec_in);
    k_gates<<<256, 256>>>(h0, W_ih, W_hh, b_ih, b_hh);
    k_lstm<<<1, 512>>>(c0, out);
    k_dec_feat<<<128, 256>>>(W_dp, b_dp);
    k_attn_gemm<<<dim3(16, 64), 256>>>(enc, W_h, coverage, w_c, v_att);
    k_softmax<<<1, 1024>>>(coverage, out);
    k_context<<<128, 256>>>(enc);
    k_out1_pgen<<<65, 256>>>(W_o1, b_o1, W_pg, b_pg, out);
    k_logits<<<(V3 + 7) / 8, 256>>>(W_o2, b_o2);
    k_vred<<<1, 1024>>>();
    k_final<<<(V3 + 255) / 256, 256>>>(out);
    k_scatter<<<16, 256>>>(in_idx, out);
}

// round 5
// speedup vs baseline: 1.1000x; 1.1000x over previous
#include <cuda_runtime.h>
#include <cuda_bf16.h>
#include <mma.h>
#include <math.h>
#include <float.h>

using namespace nvcuda;

// ---------------- problem constants ----------------
#define H    512
#define H2   1024      // 2H
#define H4   2048      // 4H
#define E    256
#define V3   50003
#define TK   4096

// output layout (flattened tuple, in order)
#define OFF_FINAL 0
#define OFF_H     (V3)                  // 50003
#define OFF_C     (OFF_H + H)           // 50515
#define OFF_CT    (OFF_C + H)           // 51027
#define OFF_ATTN  (OFF_CT + H2)         // 52051
#define OFF_PGEN  (OFF_ATTN + TK)       // 56147
#define OFF_COV   (OFF_PGEN + 1)        // 56148

// ---------------- device scratch ----------------
__device__ float g_x[E];
__device__ float g_gates[H4];
__device__ float g_h[H];
__device__ float g_c[H];
__device__ float g_dec_feat[H2];
__device__ float g_scores[TK];
__device__ float g_attn[TK];
__device__ float g_ct[H2];
__device__ float g_out1[H];
__device__ float g_logits[V3];
__device__ float g_pgen;
__device__ float g_vmax;
__device__ float g_vsum;

__device__ __forceinline__ float warp_sum(float s) {
    #pragma unroll
    for (int o = 16; o > 0; o >>= 1) s += __shfl_down_sync(0xffffffffu, s, o);
    return s;
}

__device__ __forceinline__ float sigm(float x) { return 1.0f / (1.0f + expf(-x)); }

__device__ __forceinline__ float dot4(float4 a, float4 b) {
    return a.x * b.x + a.y * b.y + a.z * b.z + a.w * b.w;
}

// ---------------- K1: x = W_xc @ [c_t_1, embd] + b_xc ----------------
__global__ __launch_bounds__(256) void k_x(
        const float* __restrict__ c_t_1, const float* __restrict__ emb,
        const float* __restrict__ W_xc, const float* __restrict__ b_xc,
        const int* __restrict__ dec_in) {
    __shared__ float sin_[H2 + E];      // 1280
    const int tid = threadIdx.x;
    const float* erow = emb + (size_t)dec_in[0] * E;
    for (int j = tid; j < H2 + E; j += 256)
        sin_[j] = (j < H2) ? c_t_1[j] : erow[j - H2];
    __syncthreads();
    const int o = blockIdx.x * 8 + (tid >> 5);
    const int lane = tid & 31;
    const float4* wr = reinterpret_cast<const float4*>(W_xc + (size_t)o * (H2 + E));
    const float4* xr = reinterpret_cast<const float4*>(sin_);
    float s = 0.f;
    #pragma unroll
    for (int i = 0; i < 10; i++) s += dot4(wr[lane + 32 * i], xr[lane + 32 * i]);
    s = warp_sum(s);
    if (lane == 0) g_x[o] = s + b_xc[o];
}

// ---------------- K2: gates = W_ih@x + W_hh@h0 + b_ih + b_hh ----------------
__global__ __launch_bounds__(256) void k_gates(
        const float* __restrict__ h0,
        const float* __restrict__ W_ih, const float* __restrict__ W_hh,
        const float* __restrict__ b_ih, const float* __restrict__ b_hh) {
    __shared__ float sx[E];
    __shared__ float sh[H];
    const int tid = threadIdx.x;
    if (tid < E) sx[tid] = g_x[tid];
    for (int j = tid; j < H; j += 256) sh[j] = h0[j];
    __syncthreads();
    const int o = blockIdx.x * 8 + (tid >> 5);
    const int lane = tid & 31;
    const float4* wi = reinterpret_cast<const float4*>(W_ih + (size_t)o * E);
    const float4* wh = reinterpret_cast<const float4*>(W_hh + (size_t)o * H);
    const float4* xr = reinterpret_cast<const float4*>(sx);
    const float4* hr = reinterpret_cast<const float4*>(sh);
    float s = 0.f;
    #pragma unroll
    for (int i = 0; i < 2; i++) s += dot4(wi[lane + 32 * i], xr[lane + 32 * i]);
    #pragma unroll
    for (int i = 0; i < 4; i++) s += dot4(wh[lane + 32 * i], hr[lane + 32 * i]);
    s = warp_sum(s);
    if (lane == 0) g_gates[o] = s + b_ih[o] + b_hh[o];
}

// ---------------- K3: LSTM combine + zero accumulators ----------------
__global__ __launch_bounds__(512) void k_lstm(const float* __restrict__ c0,
                                              float* __restrict__ out) {
    int m = threadIdx.x;           // 512 threads
    float ig = g_gates[m];
    float fg = g_gates[H + m];
    float gg = g_gates[2 * H + m];
    float og = g_gates[3 * H + m];
    float cn = sigm(fg) * c0[m] + sigm(ig) * tanhf(gg);
    float hn = sigm(og) * tanhf(cn);
    g_c[m] = cn; g_h[m] = hn;
    out[OFF_H + m] = hn;
    out[OFF_C + m] = cn;
    // zero score + context accumulators for the atomic-accumulate kernels
    #pragma unroll
    for (int t = m; t < TK; t += H) g_scores[t] = 0.f;
    g_ct[m] = 0.f; g_ct[m + H] = 0.f;
}

// ---------------- K4: dec_feat = W_dp @ [h_new, c_new] + b_dp ----------------
__global__ __launch_bounds__(256) void k_dec_feat(const float* __restrict__ W_dp,
                                                  const float* __restrict__ b_dp) {
    __shared__ float sin_[H2];
    const int tid = threadIdx.x;
    for (int j = tid; j < H2; j += 256) sin_[j] = (j < H) ? g_h[j] : g_c[j - H];
    __syncthreads();
    const int o = blockIdx.x * 8 + (tid >> 5);
    const int lane = tid & 31;
    const float4* wr = reinterpret_cast<const float4*>(W_dp + (size_t)o * H2);
    const float4* xr = reinterpret_cast<const float4*>(sin_);
    float s = 0.f;
    #pragma unroll
    for (int i = 0; i < 8; i++) s += dot4(wr[lane + 32 * i], xr[lane + 32 * i]);
    s = warp_sum(s);
    if (lane == 0) g_dec_feat[o] = s + b_dp[o];
}

// ---------------- K5: fused attention GEMM (tf32 WMMA, 128x128 tiles) ----------------
// scores[t] += sum_m v[m] * tanh( (enc @ W_h^T)[t,m] + dec_feat[m] + cov[t]*w_c[m] )
// grid (8 m-tiles, 32 t-tiles); block = 256 thr = 8 warps; warp = 64t x 32m (4x2 frags)
__global__ __launch_bounds__(256) void k_attn_gemm(
        const float* __restrict__ enc, const float* __restrict__ W_h,
        const float* __restrict__ coverage,
        const float* __restrict__ w_c, const float* __restrict__ v_att) {
    __shared__ float sbuf[9216];                 // As(128x36) | Bs(128x36); reused as Cs(64x132)
    __shared__ float sDec[128], sWc[128], sV[128], sCov[128];
    float (*As)[36]  = reinterpret_cast<float(*)[36]>(sbuf);
    float (*Bs)[36]  = reinterpret_cast<float(*)[36]>(sbuf + 128 * 36);
    float (*Cs)[132] = reinterpret_cast<float(*)[132]>(sbuf);

    const int tid = threadIdx.x;
    const int m0 = blockIdx.x * 128;
    const int t0 = blockIdx.y * 128;
    const int w  = tid >> 5;
    const int wt = w & 1;        // row half (64 t-rows)
    const int wm = w >> 1;       // col quarter (32 m-cols)

    if (tid < 128) {
        sDec[tid] = g_dec_feat[m0 + tid];
        sWc[tid]  = w_c[m0 + tid];
        sV[tid]   = v_att[m0 + tid];
        sCov[tid] = coverage[t0 + tid];
    }

    wmma::fragment<wmma::accumulator, 16, 16, 8, float> acc[4][2];
    #pragma unroll
    for (int i = 0; i < 4; i++)
        #pragma unroll
        for (int j = 0; j < 2; j++) wmma::fill_fragment(acc[i][j], 0.0f);

    const int lrow = tid >> 3;          // 0..31
    const int lf4  = (tid & 7) * 4;     // float col 0..28

    for (int k0 = 0; k0 < H2; k0 += 32) {
        __syncthreads();
        #pragma unroll
        for (int r = 0; r < 4; r++) {
            int row = lrow + r * 32;
            *reinterpret_cast<float4*>(&As[row][lf4]) =
                *reinterpret_cast<const float4*>(&enc[(size_t)(t0 + row) * H2 + k0 + lf4]);
            *reinterpret_cast<float4*>(&Bs[row][lf4]) =
                *reinterpret_cast<const float4*>(&W_h[(size_t)(m0 + row) * H2 + k0 + lf4]);
        }
        __syncthreads();

        #pragma unroll
        for (int kk = 0; kk < 32; kk += 8) {
            wmma::fragment<wmma::matrix_a, 16, 16, 8, wmma::precision::tf32, wmma::row_major> a[4];
            wmma::fragment<wmma::matrix_b, 16, 16, 8, wmma::precision::tf32, wmma::col_major> b[2];
            #pragma unroll
            for (int i = 0; i < 4; i++) {
                wmma::load_matrix_sync(a[i], &As[wt * 64 + i * 16][kk], 36);
                #pragma unroll
                for (int e = 0; e < a[i].num_elements; e++) a[i].x[e] = wmma::__float_to_tf32(a[i].x[e]);
            }
            #pragma unroll
            for (int j = 0; j < 2; j++) {
                wmma::load_matrix_sync(b[j], &Bs[wm * 32 + j * 16][kk], 36);
                #pragma unroll
                for (int e = 0; e < b[j].num_elements; e++) b[j].x[e] = wmma::__float_to_tf32(b[j].x[e]);
            }
            #pragma unroll
            for (int i = 0; i < 4; i++)
                #pragma unroll
                for (int j = 0; j < 2; j++)
                    wmma::mma_sync(acc[i][j], a[i], b[j], acc[i][j]);
        }
    }

    // epilogue in two row-halves, reusing sbuf as Cs[64][132]
    #pragma unroll
    for (int half = 0; half < 2; half++) {
        __syncthreads();
        if (wt == half) {
            #pragma unroll
            for (int i = 0; i < 4; i++)
                #pragma unroll
                for (int j = 0; j < 2; j++)
                    wmma::store_matrix_sync(&Cs[i * 16][wm * 32 + j * 16], acc[i][j],
                                            132, wmma::mem_row_major);
        }
        __syncthreads();
        const int tr = tid >> 2;        // 0..63
        const int q  = tid & 3;         // 0..3 (32 m each)
        const float cov = sCov[half * 64 + tr];
        float s = 0.f;
        #pragma unroll
        for (int mm = q * 32; mm < q * 32 + 32; mm++)
            s += sV[mm] * tanhf(Cs[tr][mm] + sDec[mm] + cov * sWc[mm]);
        s += __shfl_down_sync(0xffffffffu, s, 2, 4);
        s += __shfl_down_sync(0xffffffffu, s, 1, 4);
        if (q == 0) atomicAdd(&g_scores[t0 + half * 64 + tr], s);
    }
}

// ---------------- K6: softmax over scores -> attn, coverage_next ----------------
__global__ __launch_bounds__(1024) void k_softmax(const float* __restrict__ coverage,
                                                  float* __restrict__ out) {
    __shared__ float red[32];
    __shared__ float ebuf[TK];
    const int tid = threadIdx.x;   // 1024 threads
    float v[4];
    float lm = -FLT_MAX;
    #pragma unroll
    for (int i = 0; i < 4; i++) { v[i] = g_scores[tid + i * 1024]; lm = fmaxf(lm, v[i]); }
    #pragma unroll
    for (int o = 16; o > 0; o >>= 1) lm = fmaxf(lm, __shfl_down_sync(0xffffffffu, lm, o));
    if ((tid & 31) == 0) red[tid >> 5] = lm;
    __syncthreads();
    if (tid < 32) {
        float x = red[tid];
        #pragma unroll
        for (int o = 16; o > 0; o >>= 1) x = fmaxf(x, __shfl_down_sync(0xffffffffu, x, o));
        if (tid == 0) red[0] = x;
    }
    __syncthreads();
    const float mx = red[0];
    __syncthreads();
    float ls = 0.f;
    #pragma unroll
    for (int i = 0; i < 4; i++) { float e = expf(v[i] - mx); ebuf[tid + i * 1024] = e; ls += e; }
    ls = warp_sum(ls);
    if ((tid & 31) == 0) red[tid >> 5] = ls;
    __syncthreads();
    if (tid < 32) {
        float x = red[tid];
        x = warp_sum(x);
        if (tid == 0) red[0] = x;
    }
    __syncthreads();
    const float inv = 1.0f / red[0];
    #pragma unroll
    for (int i = 0; i < 4; i++) {
        int idx = tid + i * 1024;
        float a = ebuf[idx] * inv;
        g_attn[idx] = a;
        out[OFF_ATTN + idx] = a;
        out[OFF_COV + idx]  = coverage[idx] + a;
    }
}

// ---------------- K7: c_t = attn @ enc (partial accumulate) ----------------
__global__ __launch_bounds__(256) void k_context(const float* __restrict__ enc) {
    const int t0 = blockIdx.x * 32;      // 128 blocks x 32 timesteps
    const int nb = threadIdx.x * 4;      // 256 threads cover 1024 cols
    float4 acc = make_float4(0.f, 0.f, 0.f, 0.f);
    #pragma unroll
    for (int tt = 0; tt < 32; tt++) {
        float a = g_attn[t0 + tt];
        float4 e = *reinterpret_cast<const float4*>(enc + (size_t)(t0 + tt) * H2 + nb);
        acc.x += a * e.x; acc.y += a * e.y; acc.z += a * e.z; acc.w += a * e.w;
    }
    atomicAdd(&g_ct[nb + 0], acc.x);
    atomicAdd(&g_ct[nb + 1], acc.y);
    atomicAdd(&g_ct[nb + 2], acc.z);
    atomicAdd(&g_ct[nb + 3], acc.w);
}

// ---------------- K8: out1 rows (blocks 0..63) + p_gen & c_t writeout (block 64) ----------------
__global__ __launch_bounds__(256) void k_out1_pgen(
        const float* __restrict__ W_o1, const float* __restrict__ b_o1,
        const float* __restrict__ W_pg, const float* __restrict__ b_pg,
        float* __restrict__ out) {
    const int tid = threadIdx.x;
    if (blockIdx.x < 64) {
        __shared__ float sin_[3 * H];
        for (int j = tid; j < 3 * H; j += 256) sin_[j] = (j < H) ? g_h[j] : g_ct[j - H];
        __syncthreads();
        const int o = blockIdx.x * 8 + (tid >> 5);
        const int lane = tid & 31;
        const float4* wr = reinterpret_cast<const float4*>(W_o1 + (size_t)o * (3 * H));
        const float4* xr = reinterpret_cast<const float4*>(sin_);
        float s = 0.f;
        #pragma unroll
        for (int i = 0; i < 12; i++) s += dot4(wr[lane + 32 * i], xr[lane + 32 * i]);
        s = warp_sum(s);
        if (lane == 0) g_out1[o] = s + b_o1[o];
    } else {
        __shared__ float red[8];
        float s = 0.f;
        for (int j = tid; j < H4 + E; j += 256) {
            float v;
            if (j < H2)            v = g_ct[j];
            else if (j < H2 + H)   v = g_h[j - H2];
            else if (j < H4)       v = g_c[j - H2 - H];
            else                   v = g_x[j - H4];
            s += W_pg[j] * v;
        }
        s = warp_sum(s);
        if ((tid & 31) == 0) red[tid >> 5] = s;
        __syncthreads();
        if (tid == 0) {
            float x = 0.f;
            #pragma unroll
            for (int i = 0; i < 8; i++) x += red[i];
            float p = sigm(x + b_pg[0]);
            g_pgen = p; out[OFF_PGEN] = p;
        }
        #pragma unroll
        for (int i = 0; i < 4; i++) out[OFF_CT + tid * 4 + i] = g_ct[tid * 4 + i];
    }
}

// ---------------- K9: logits = W_o2 @ out1 + b_o2 (2 rows per warp) ----------------
__global__ __launch_bounds__(256) void k_logits(const float* __restrict__ W_o2,
                                                const float* __restrict__ b_o2) {
    __shared__ float sx[H];
    const int tid = threadIdx.x;
    sx[tid] = g_out1[tid]; sx[tid + 256] = g_out1[tid + 256];
    __syncthreads();
    const int w = tid >> 5, lane = tid & 31;
    const int v0 = blockIdx.x * 16 + w * 2;
    if (v0 < V3) {
        const bool has1 = (v0 + 1 < V3);
        const float4* w0 = reinterpret_cast<const float4*>(W_o2 + (size_t)v0 * H);
        const float4* w1 = reinterpret_cast<const float4*>(W_o2 + (size_t)(v0 + (has1 ? 1 : 0)) * H);
        const float4* xr = reinterpret_cast<const float4*>(sx);
        float s0 = 0.f, s1 = 0.f;
        #pragma unroll
        for (int i = 0; i < 4; i++) {
            float4 x4 = xr[lane + 32 * i];
            s0 += dot4(w0[lane + 32 * i], x4);
            s1 += dot4(w1[lane + 32 * i], x4);
        }
        s0 = warp_sum(s0);
        s1 = warp_sum(s1);
        if (lane == 0) {
            g_logits[v0] = s0 + b_o2[v0];
            if (has1) g_logits[v0 + 1] = s1 + b_o2[v0 + 1];
        }
    }
}

// ---------------- K10: vocab softmax reduction (max, sumexp) ----------------
__global__ __launch_bounds__(1024) void k_vred() {
    __shared__ float red[32];
    const int tid = threadIdx.x;  // 1024
    float lm = -FLT_MAX;
    for (int v = tid; v < V3; v += 1024) lm = fmaxf(lm, g_logits[v]);
    #pragma unroll
    for (int o = 16; o > 0; o >>= 1) lm = fmaxf(lm, __shfl_down_sync(0xffffffffu, lm, o));
    if ((tid & 31) == 0) red[tid >> 5] = lm;
    __syncthreads();
    if (tid < 32) {
        float x = red[tid];
        #pragma unroll
        for (int o = 16; o > 0; o >>= 1) x = fmaxf(x, __shfl_down_sync(0xffffffffu, x, o));
        if (tid == 0) red[0] = x;
    }
    __syncthreads();
    const float mx = red[0];
    __syncthreads();
    float ls = 0.f;
    for (int v = tid; v < V3; v += 1024) ls += expf(g_logits[v] - mx);
    ls = warp_sum(ls);
    if ((tid & 31) == 0) red[tid >> 5] = ls;
    __syncthreads();
    if (tid < 32) {
        float x = red[tid];
        x = warp_sum(x);
        if (tid == 0) { g_vmax = mx; g_vsum = x; }
    }
}

// ---------------- K11: final_dist base = p_gen * vocab_softmax ----------------
__global__ __launch_bounds__(256) void k_final(float* __restrict__ out) {
    int v = blockIdx.x * blockDim.x + threadIdx.x;
    if (v < V3) out[v] = g_pgen * expf(g_logits[v] - g_vmax) / g_vsum;
}

// ---------------- K12: scatter add (1-p_gen)*attn at input_idx ----------------
__global__ __launch_bounds__(256) void k_scatter(const int* __restrict__ input_idx,
                                                 float* __restrict__ out) {
    int t = blockIdx.x * blockDim.x + threadIdx.x;
    if (t < TK) atomicAdd(&out[input_idx[t]], (1.0f - g_pgen) * g_attn[t]);
}

// ---------------- launch ----------------
extern "C" void kernel_launch(void* const* d_in, const int* in_sizes, int n_in,
                              void* d_out, int out_size) {
    const float* enc      = (const float*)d_in[0];
    const float* c_t_1    = (const float*)d_in[1];
    const float* h0       = (const float*)d_in[2];
    const float* c0       = (const float*)d_in[3];
    const float* coverage = (const float*)d_in[4];
    const float* emb      = (const float*)d_in[5];
    const float* W_xc     = (const float*)d_in[6];
    const float* b_xc     = (const float*)d_in[7];
    const float* W_ih     = (const float*)d_in[8];
    const float* W_hh     = (const float*)d_in[9];
    const float* b_ih     = (const float*)d_in[10];
    const float* b_hh     = (const float*)d_in[11];
    const float* W_h      = (const float*)d_in[12];
    const float* W_dp     = (const float*)d_in[13];
    const float* b_dp     = (const float*)d_in[14];
    const float* w_c      = (const float*)d_in[15];
    const float* v_att    = (const float*)d_in[16];
    const float* W_pg     = (const float*)d_in[17];
    const float* b_pg     = (const float*)d_in[18];
    const float* W_o1     = (const float*)d_in[19];
    const float* b_o1     = (const float*)d_in[20];
    const float* W_o2     = (const float*)d_in[21];
    const float* b_o2     = (const float*)d_in[22];
    const int*   dec_in   = (const int*)d_in[23];
    const int*   in_idx   = (const int*)d_in[24];
    float* out = (float*)d_out;

    k_x<<<32, 256>>>(c_t_1, emb, W_xc, b_xc, dec_in);
    k_gates<<<256, 256>>>(h0, W_ih, W_hh, b_ih, b_hh);
    k_lstm<<<1, 512>>>(c0, out);
    k_dec_feat<<<128, 256>>>(W_dp, b_dp);
    k_attn_gemm<<<dim3(8, 32), 256>>>(enc, W_h, coverage, w_c, v_att);
    k_softmax<<<1, 1024>>>(coverage, out);
    k_context<<<128, 256>>>(enc);
    k_out1_pgen<<<65, 256>>>(W_o1, b_o1, W_pg, b_pg, out);
    k_logits<<<(V3 + 15) / 16, 256>>>(W_o2, b_o2);
    k_vred<<<1, 1024>>>();
    k_final<<<(V3 + 255) / 256, 256>>>(out);
    k_scatter<<<16, 256>>>(in_idx, out);
}

// round 7
// speedup vs baseline: 1.2355x; 1.1233x over previous
#include <cuda_runtime.h>
#include <cuda_bf16.h>
#include <mma.h>
#include <math.h>
#include <float.h>
#include <stdint.h>

using namespace nvcuda;

// ---------------- problem constants ----------------
#define H    512
#define H2   1024      // 2H
#define H4   2048      // 4H
#define E    256
#define V3   50003
#define TK   4096

// output layout (flattened tuple, in order)
#define OFF_FINAL 0
#define OFF_H     (V3)                  // 50003
#define OFF_C     (OFF_H + H)           // 50515
#define OFF_CT    (OFF_C + H)           // 51027
#define OFF_ATTN  (OFF_CT + H2)         // 52051
#define OFF_PGEN  (OFF_ATTN + TK)      // 56147
#define OFF_COV   (OFF_PGEN + 1)        // 56148

// ---------------- device scratch ----------------
__device__ float g_x[E];
__device__ float g_gates[H4];
__device__ float g_h[H];
__device__ float g_c[H];
__device__ float g_dec_feat[H2];
__device__ float g_enc_feat[TK * H2];   // 16 MB GEMM output (L2-resident)
__device__ float g_scores[TK];
__device__ float g_attn[TK];
__device__ float g_ct[H2];
__device__ float g_out1[H];
__device__ float g_logits[V3];
__device__ float g_pgen;
__device__ float g_vmax;
__device__ float g_vsum;

__device__ __forceinline__ float warp_sum(float s) {
    #pragma unroll
    for (int o = 16; o > 0; o >>= 1) s += __shfl_down_sync(0xffffffffu, s, o);
    return s;
}

__device__ __forceinline__ float sigm(float x) { return 1.0f / (1.0f + expf(-x)); }

__device__ __forceinline__ float dot4(float4 a, float4 b) {
    return a.x * b.x + a.y * b.y + a.z * b.z + a.w * b.w;
}

__device__ __forceinline__ void cp_async16(void* smem_dst, const void* gmem_src) {
    unsigned int s = (unsigned int)__cvta_generic_to_shared(smem_dst);
    asm volatile("cp.async.cg.shared.global [%0], [%1], 16;\n" :: "r"(s), "l"(gmem_src));
}

// ---------------- K1: x = W_xc @ [c_t_1, embd] + b_xc ----------------
__global__ __launch_bounds__(256) void k_x(
        const float* __restrict__ c_t_1, const float* __restrict__ emb,
        const float* __restrict__ W_xc, const float* __restrict__ b_xc,
        const int* __restrict__ dec_in) {
    __shared__ float sin_[H2 + E];      // 1280
    const int tid = threadIdx.x;
    const float* erow = emb + (size_t)dec_in[0] * E;
    for (int j = tid; j < H2 + E; j += 256)
        sin_[j] = (j < H2) ? c_t_1[j] : erow[j - H2];
    __syncthreads();
    const int o = blockIdx.x * 8 + (tid >> 5);
    const int lane = tid & 31;
    const float4* wr = reinterpret_cast<const float4*>(W_xc + (size_t)o * (H2 + E));
    const float4* xr = reinterpret_cast<const float4*>(sin_);
    float4 wv[10];
    #pragma unroll
    for (int i = 0; i < 10; i++) wv[i] = wr[lane + 32 * i];   // batched LDGs
    float s = 0.f;
    #pragma unroll
    for (int i = 0; i < 10; i++) s += dot4(wv[i], xr[lane + 32 * i]);
    s = warp_sum(s);
    if (lane == 0) g_x[o] = s + b_xc[o];
}

// ---------------- K2: gates = W_ih@x + W_hh@h0 + b_ih + b_hh ----------------
__global__ __launch_bounds__(256) void k_gates(
        const float* __restrict__ h0,
        const float* __restrict__ W_ih, const float* __restrict__ W_hh,
        const float* __restrict__ b_ih, const float* __restrict__ b_hh) {
    __shared__ float sx[E];
    __shared__ float sh[H];
    const int tid = threadIdx.x;
    if (tid < E) sx[tid] = g_x[tid];
    for (int j = tid; j < H; j += 256) sh[j] = h0[j];
    __syncthreads();
    const int o = blockIdx.x * 8 + (tid >> 5);
    const int lane = tid & 31;
    const float4* wi = reinterpret_cast<const float4*>(W_ih + (size_t)o * E);
    const float4* wh = reinterpret_cast<const float4*>(W_hh + (size_t)o * H);
    const float4* xr = reinterpret_cast<const float4*>(sx);
    const float4* hr = reinterpret_cast<const float4*>(sh);
    float4 wv[6];
    #pragma unroll
    for (int i = 0; i < 2; i++) wv[i] = wi[lane + 32 * i];
    #pragma unroll
    for (int i = 0; i < 4; i++) wv[2 + i] = wh[lane + 32 * i];
    float s = 0.f;
    #pragma unroll
    for (int i = 0; i < 2; i++) s += dot4(wv[i], xr[lane + 32 * i]);
    #pragma unroll
    for (int i = 0; i < 4; i++) s += dot4(wv[2 + i], hr[lane + 32 * i]);
    s = warp_sum(s);
    if (lane == 0) g_gates[o] = s + b_ih[o] + b_hh[o];
}

// ---------------- K3: LSTM combine + zero ct accumulator ----------------
__global__ __launch_bounds__(512) void k_lstm(const float* __restrict__ c0,
                                              float* __restrict__ out) {
    int m = threadIdx.x;           // 512 threads
    float ig = g_gates[m];
    float fg = g_gates[H + m];
    float gg = g_gates[2 * H + m];
    float og = g_gates[3 * H + m];
    float cn = sigm(fg) * c0[m] + sigm(ig) * tanhf(gg);
    float hn = sigm(og) * tanhf(cn);
    g_c[m] = cn; g_h[m] = hn;
    out[OFF_H + m] = hn;
    out[OFF_C + m] = cn;
    g_ct[m] = 0.f; g_ct[m + H] = 0.f;
}

// ---------------- K4: pure GEMM  enc_feat = enc @ W_h^T  (tf32 WMMA, cp.async) ----
// 128x128 tiles, K-chunk 32, 2-stage double buffer in dynamic smem (72 KB).
// No float->tf32 conversion (HW truncates; error well within budget).
#define MM_STAGE 9216                   // floats per stage: As(128x36)+Bs(128x36)
__global__ __launch_bounds__(256) void k_attn_mm(
        const float* __restrict__ enc, const float* __restrict__ W_h) {
    extern __shared__ float dynbuf[];   // 2 * MM_STAGE floats

    const int tid = threadIdx.x;
    const int m0 = blockIdx.x * 128;
    const int t0 = blockIdx.y * 128;
    const int w  = tid >> 5;
    const int wt = w & 1;        // row half (64 t-rows)
    const int wm = w >> 1;       // col quarter (32 m-cols)

    const int lrow = tid >> 3;          // 0..31
    const int lf4  = (tid & 7) * 4;     // float col 0,4,..,28

    wmma::fragment<wmma::accumulator, 16, 16, 8, float> acc[4][2];
    #pragma unroll
    for (int i = 0; i < 4; i++)
        #pragma unroll
        for (int j = 0; j < 2; j++) wmma::fill_fragment(acc[i][j], 0.0f);

    // prefetch chunk 0 into stage 0
    {
        float* As = dynbuf;
        float* Bs = dynbuf + 128 * 36;
        #pragma unroll
        for (int r = 0; r < 4; r++) {
            int row = lrow + r * 32;
            cp_async16(&As[row * 36 + lf4], &enc[(size_t)(t0 + row) * H2 + lf4]);
            cp_async16(&Bs[row * 36 + lf4], &W_h[(size_t)(m0 + row) * H2 + lf4]);
        }
        asm volatile("cp.async.commit_group;\n" ::);
    }

    for (int c = 0; c < 32; c++) {
        if (c + 1 < 32) {
            float* As = dynbuf + ((c + 1) & 1) * MM_STAGE;
            float* Bs = As + 128 * 36;
            const int k0 = (c + 1) * 32;
            #pragma unroll
            for (int r = 0; r < 4; r++) {
                int row = lrow + r * 32;
                cp_async16(&As[row * 36 + lf4], &enc[(size_t)(t0 + row) * H2 + k0 + lf4]);
                cp_async16(&Bs[row * 36 + lf4], &W_h[(size_t)(m0 + row) * H2 + k0 + lf4]);
            }
            asm volatile("cp.async.commit_group;\n" ::);
            asm volatile("cp.async.wait_group 1;\n" ::);
        } else {
            asm volatile("cp.async.wait_group 0;\n" ::);
        }
        __syncthreads();

        const float* As = dynbuf + (c & 1) * MM_STAGE;
        const float* Bs = As + 128 * 36;
        #pragma unroll
        for (int kk = 0; kk < 32; kk += 8) {
            wmma::fragment<wmma::matrix_a, 16, 16, 8, wmma::precision::tf32, wmma::row_major> a[4];
            wmma::fragment<wmma::matrix_b, 16, 16, 8, wmma::precision::tf32, wmma::col_major> b[2];
            #pragma unroll
            for (int i = 0; i < 4; i++)
                wmma::load_matrix_sync(a[i], &As[(wt * 64 + i * 16) * 36 + kk], 36);
            #pragma unroll
            for (int j = 0; j < 2; j++)
                wmma::load_matrix_sync(b[j], &Bs[(wm * 32 + j * 16) * 36 + kk], 36);
            #pragma unroll
            for (int i = 0; i < 4; i++)
                #pragma unroll
                for (int j = 0; j < 2; j++)
                    wmma::mma_sync(acc[i][j], a[i], b[j], acc[i][j]);
        }
        __syncthreads();
    }

    // store C tile straight to gmem (fp32, ld = 1024)
    #pragma unroll
    for (int i = 0; i < 4; i++)
        #pragma unroll
        for (int j = 0; j < 2; j++) {
            int row = t0 + wt * 64 + i * 16;
            int col = m0 + wm * 32 + j * 16;
            wmma::store_matrix_sync(&g_enc_feat[(size_t)row * H2 + col], acc[i][j],
                                    H2, wmma::mem_row_major);
        }
}

// ---------------- K5: dec_feat = W_dp @ [h_new, c_new] + b_dp ----------------
__global__ __launch_bounds__(256) void k_dec_feat(const float* __restrict__ W_dp,
                                                  const float* __restrict__ b_dp) {
    __shared__ float sin_[H2];
    const int tid = threadIdx.x;
    for (int j = tid; j < H2; j += 256) sin_[j] = (j < H) ? g_h[j] : g_c[j - H];
    __syncthreads();
    const int o = blockIdx.x * 8 + (tid >> 5);
    const int lane = tid & 31;
    const float4* wr = reinterpret_cast<const float4*>(W_dp + (size_t)o * H2);
    const float4* xr = reinterpret_cast<const float4*>(sin_);
    float4 wv[8];
    #pragma unroll
    for (int i = 0; i < 8; i++) wv[i] = wr[lane + 32 * i];    // batched LDGs
    float s = 0.f;
    #pragma unroll
    for (int i = 0; i < 8; i++) s += dot4(wv[i], xr[lane + 32 * i]);
    s = warp_sum(s);
    if (lane == 0) g_dec_feat[o] = s + b_dp[o];
}

// ---------------- K6: epilogue  scores[t] = sum_m v[m]*tanh(ef[t,m]+dec[m]+cov[t]*wc[m]) --
__global__ __launch_bounds__(256) void k_attn_epi(
        const float* __restrict__ coverage,
        const float* __restrict__ w_c, const float* __restrict__ v_att) {
    __shared__ float sDec[H2], sWc[H2], sV[H2];
    const int tid = threadIdx.x;
    for (int j = tid; j < H2; j += 256) {
        sDec[j] = g_dec_feat[j];
        sWc[j]  = w_c[j];
        sV[j]   = v_att[j];
    }
    __syncthreads();
    const int w = tid >> 5, lane = tid & 31;
    const float4* dec4 = reinterpret_cast<const float4*>(sDec);
    const float4* wc4  = reinterpret_cast<const float4*>(sWc);
    const float4* v4   = reinterpret_cast<const float4*>(sV);
    #pragma unroll
    for (int pass = 0; pass < 8; pass++) {
        const int t = blockIdx.x * 64 + pass * 8 + w;
        const float cov = coverage[t];
        const float4* row = reinterpret_cast<const float4*>(g_enc_feat + (size_t)t * H2);
        float s = 0.f;
        #pragma unroll
        for (int i = 0; i < 8; i++) {
            const int q = lane + 32 * i;
            float4 e = row[q];
            float4 d = dec4[q], wc = wc4[q], vv = v4[q];
            s += vv.x * tanhf(e.x + d.x + cov * wc.x);
            s += vv.y * tanhf(e.y + d.y + cov * wc.y);
            s += vv.z * tanhf(e.z + d.z + cov * wc.z);
            s += vv.w * tanhf(e.w + d.w + cov * wc.w);
        }
        s = warp_sum(s);
        if (lane == 0) g_scores[t] = s;
    }
}

// ---------------- K7: softmax over scores -> attn, coverage_next ----------------
__global__ __launch_bounds__(1024) void k_softmax(const float* __restrict__ coverage,
                                                  float* __restrict__ out) {
    __shared__ float red[32];
    __shared__ float ebuf[TK];
    const int tid = threadIdx.x;   // 1024 threads
    float v[4];
    float lm = -FLT_MAX;
    #pragma unroll
    for (int i = 0; i < 4; i++) { v[i] = g_scores[tid + i * 1024]; lm = fmaxf(lm, v[i]); }
    #pragma unroll
    for (int o = 16; o > 0; o >>= 1) lm = fmaxf(lm, __shfl_down_sync(0xffffffffu, lm, o));
    if ((tid & 31) == 0) red[tid >> 5] = lm;
    __syncthreads();
    if (tid < 32) {
        float x = red[tid];
        #pragma unroll
        for (int o = 16; o > 0; o >>= 1) x = fmaxf(x, __shfl_down_sync(0xffffffffu, x, o));
        if (tid == 0) red[0] = x;
    }
    __syncthreads();
    const float mx = red[0];
    __syncthreads();
    float ls = 0.f;
    #pragma unroll
    for (int i = 0; i < 4; i++) { float e = expf(v[i] - mx); ebuf[tid + i * 1024] = e; ls += e; }
    ls = warp_sum(ls);
    if ((tid & 31) == 0) red[tid >> 5] = ls;
    __syncthreads();
    if (tid < 32) {
        float x = red[tid];
        x = warp_sum(x);
        if (tid == 0) red[0] = x;
    }
    __syncthreads();
    const float inv = 1.0f / red[0];
    #pragma unroll
    for (int i = 0; i < 4; i++) {
        int idx = tid + i * 1024;
        float a = ebuf[idx] * inv;
        g_attn[idx] = a;
        out[OFF_ATTN + idx] = a;
        out[OFF_COV + idx]  = coverage[idx] + a;
    }
}

// ---------------- K8: c_t = attn @ enc (partial accumulate) ----------------
__global__ __launch_bounds__(256) void k_context(const float* __restrict__ enc) {
    const int t0 = blockIdx.x * 32;      // 128 blocks x 32 timesteps
    const int nb = threadIdx.x * 4;      // 256 threads cover 1024 cols
    float4 acc = make_float4(0.f, 0.f, 0.f, 0.f);
    #pragma unroll
    for (int tt = 0; tt < 32; tt++) {
        float a = g_attn[t0 + tt];
        float4 e = *reinterpret_cast<const float4*>(enc + (size_t)(t0 + tt) * H2 + nb);
        acc.x += a * e.x; acc.y += a * e.y; acc.z += a * e.z; acc.w += a * e.w;
    }
    atomicAdd(&g_ct[nb + 0], acc.x);
    atomicAdd(&g_ct[nb + 1], acc.y);
    atomicAdd(&g_ct[nb + 2], acc.z);
    atomicAdd(&g_ct[nb + 3], acc.w);
}

// ---------------- K9: out1 rows (blocks 0..63) + p_gen & c_t writeout (block 64) ----
__global__ __launch_bounds__(256) void k_out1_pgen(
        const float* __restrict__ W_o1, const float* __restrict__ b_o1,
        const float* __restrict__ W_pg, const float* __restrict__ b_pg,
        float* __restrict__ out) {
    const int tid = threadIdx.x;
    if (blockIdx.x < 64) {
        __shared__ float sin_[3 * H];
        for (int j = tid; j < 3 * H; j += 256) sin_[j] = (j < H) ? g_h[j] : g_ct[j - H];
        __syncthreads();
        const int o = blockIdx.x * 8 + (tid >> 5);
        const int lane = tid & 31;
        const float4* wr = reinterpret_cast<const float4*>(W_o1 + (size_t)o * (3 * H));
        const float4* xr = reinterpret_cast<const float4*>(sin_);
        float4 wv[12];
        #pragma unroll
        for (int i = 0; i < 12; i++) wv[i] = wr[lane + 32 * i];   // batched LDGs
        float s = 0.f;
        #pragma unroll
        for (int i = 0; i < 12; i++) s += dot4(wv[i], xr[lane + 32 * i]);
        s = warp_sum(s);
        if (lane == 0) g_out1[o] = s + b_o1[o];
    } else {
        __shared__ float red[8];
        float s = 0.f;
        for (int j = tid; j < H4 + E; j += 256) {
            float v;
            if (j < H2)            v = g_ct[j];
            else if (j < H2 + H)   v = g_h[j - H2];
            else if (j < H4)       v = g_c[j - H2 - H];
            else                   v = g_x[j - H4];
            s += W_pg[j] * v;
        }
        s = warp_sum(s);
        if ((tid & 31) == 0) red[tid >> 5] = s;
        __syncthreads();
        if (tid == 0) {
            float x = 0.f;
            #pragma unroll
            for (int i = 0; i < 8; i++) x += red[i];
            float p = sigm(x + b_pg[0]);
            g_pgen = p; out[OFF_PGEN] = p;
        }
        #pragma unroll
        for (int i = 0; i < 4; i++) out[OFF_CT + tid * 4 + i] = g_ct[tid * 4 + i];
    }
}

// ---------------- K10: logits = W_o2 @ out1 + b_o2 (2 rows per warp) ----------------
__global__ __launch_bounds__(256) void k_logits(const float* __restrict__ W_o2,
                                                const float* __restrict__ b_o2) {
    __shared__ float sx[H];
    const int tid = threadIdx.x;
    sx[tid] = g_out1[tid]; sx[tid + 256] = g_out1[tid + 256];
    __syncthreads();
    const int w = tid >> 5, lane = tid & 31;
    const int v0 = blockIdx.x * 16 + w * 2;
    if (v0 < V3) {
        const bool has1 = (v0 + 1 < V3);
        const float4* w0 = reinterpret_cast<const float4*>(W_o2 + (size_t)v0 * H);
        const float4* w1 = reinterpret_cast<const float4*>(W_o2 + (size_t)(v0 + (has1 ? 1 : 0)) * H);
        const float4* xr = reinterpret_cast<const float4*>(sx);
        float4 wv0[4], wv1[4];
        #pragma unroll
        for (int i = 0; i < 4; i++) { wv0[i] = w0[lane + 32 * i]; wv1[i] = w1[lane + 32 * i]; }
        float s0 = 0.f, s1 = 0.f;
        #pragma unroll
        for (int i = 0; i < 4; i++) {
            float4 x4 = xr[lane + 32 * i];
            s0 += dot4(wv0[i], x4);
            s1 += dot4(wv1[i], x4);
        }
        s0 = warp_sum(s0);
        s1 = warp_sum(s1);
        if (lane == 0) {
            g_logits[v0] = s0 + b_o2[v0];
            if (has1) g_logits[v0 + 1] = s1 + b_o2[v0 + 1];
        }
    }
}

// ---------------- K11: vocab softmax reduction (max, sumexp) ----------------
__global__ __launch_bounds__(1024) void k_vred() {
    __shared__ float red[32];
    const int tid = threadIdx.x;  // 1024
    float lm = -FLT_MAX;
    for (int v = tid; v < V3; v += 1024) lm = fmaxf(lm, g_logits[v]);
    #pragma unroll
    for (int o = 16; o > 0; o >>= 1) lm = fmaxf(lm, __shfl_down_sync(0xffffffffu, lm, o));
    if ((tid & 31) == 0) red[tid >> 5] = lm;
    __syncthreads();
    if (tid < 32) {
        float x = red[tid];
        #pragma unroll
        for (int o = 16; o > 0; o >>= 1) x = fmaxf(x, __shfl_down_sync(0xffffffffu, x, o));
        if (tid == 0) red[0] = x;
    }
    __syncthreads();
    const float mx = red[0];
    __syncthreads();
    float ls = 0.f;
    for (int v = tid; v < V3; v += 1024) ls += expf(g_logits[v] - mx);
    ls = warp_sum(ls);
    if ((tid & 31) == 0) red[tid >> 5] = ls;
    __syncthreads();
    if (tid < 32) {
        float x = red[tid];
        x = warp_sum(x);
        if (tid == 0) { g_vmax = mx; g_vsum = x; }
    }
}

// ---------------- K12: final_dist base = p_gen * vocab_softmax ----------------
__global__ __launch_bounds__(256) void k_final(float* __restrict__ out) {
    int v = blockIdx.x * blockDim.x + threadIdx.x;
    if (v < V3) out[v] = g_pgen * expf(g_logits[v] - g_vmax) / g_vsum;
}

// ---------------- K13: scatter add (1-p_gen)*attn at input_idx ----------------
__global__ __launch_bounds__(256) void k_scatter(const int* __restrict__ input_idx,
                                                 float* __restrict__ out) {
    int t = blockIdx.x * blockDim.x + threadIdx.x;
    if (t < TK) atomicAdd(&out[input_idx[t]], (1.0f - g_pgen) * g_attn[t]);
}

// ---------------- launch ----------------
extern "C" void kernel_launch(void* const* d_in, const int* in_sizes, int n_in,
                              void* d_out, int out_size) {
    const float* enc      = (const float*)d_in[0];
    const float* c_t_1    = (const float*)d_in[1];
    const float* h0       = (const float*)d_in[2];
    const float* c0       = (const float*)d_in[3];
    const float* coverage = (const float*)d_in[4];
    const float* emb      = (const float*)d_in[5];
    const float* W_xc     = (const float*)d_in[6];
    const float* b_xc     = (const float*)d_in[7];
    const float* W_ih     = (const float*)d_in[8];
    const float* W_hh     = (const float*)d_in[9];
    const float* b_ih     = (const float*)d_in[10];
    const float* b_hh     = (const float*)d_in[11];
    const float* W_h      = (const float*)d_in[12];
    const float* W_dp     = (const float*)d_in[13];
    const float* b_dp     = (const float*)d_in[14];
    const float* w_c      = (const float*)d_in[15];
    const float* v_att    = (const float*)d_in[16];
    const float* W_pg     = (const float*)d_in[17];
    const float* b_pg     = (const float*)d_in[18];
    const float* W_o1     = (const float*)d_in[19];
    const float* b_o1     = (const float*)d_in[20];
    const float* W_o2     = (const float*)d_in[21];
    const float* b_o2     = (const float*)d_in[22];
    const int*   dec_in   = (const int*)d_in[23];
    const int*   in_idx   = (const int*)d_in[24];
    float* out = (float*)d_out;

    cudaFuncSetAttribute(k_attn_mm, cudaFuncAttributeMaxDynamicSharedMemorySize,
                         2 * MM_STAGE * (int)sizeof(float));

    k_x<<<32, 256>>>(c_t_1, emb, W_xc, b_xc, dec_in);                       // 1
    k_gates<<<256, 256>>>(h0, W_ih, W_hh, b_ih, b_hh);                      // 2
    k_lstm<<<1, 512>>>(c0, out);                                            // 3
    k_attn_mm<<<dim3(8, 32), 256, 2 * MM_STAGE * sizeof(float)>>>(enc, W_h);// 4 (ncu capture)
    k_dec_feat<<<128, 256>>>(W_dp, b_dp);                                   // 5
    k_attn_epi<<<64, 256>>>(coverage, w_c, v_att);                          // 6
    k_softmax<<<1, 1024>>>(coverage, out);                                  // 7
    k_context<<<128, 256>>>(enc);                                           // 8
    k_out1_pgen<<<65, 256>>>(W_o1, b_o1, W_pg, b_pg, out);                  // 9
    k_logits<<<(V3 + 15) / 16, 256>>>(W_o2, b_o2);                          // 10
    k_vred<<<1, 1024>>>();                                                  // 11
    k_final<<<(V3 + 255) / 256, 256>>>(out);                                // 12
    k_scatter<<<16, 256>>>(in_idx, out);                                    // 13
}